// round 16
// baseline (speedup 1.0000x reference)
#include <cuda_runtime.h>
#include <cuda_fp16.h>
#include <cstdint>

#define EPSF 1e-8f

static constexpr int IN  = 256;
static constexpr int OUT = 256;
static constexpr int G   = 5;
static constexpr int K   = IN * G;    // 1280
static constexpr int BQ  = 32768;

// GEMM tiling: BM=128, BN=256(full OUT), 8 warps of 64x64
static constexpr int BM = 128;
static constexpr int BN = 256;
static constexpr int BK = 64;         // halves per chunk = 128B rows
static constexpr int NCH = K / BK;    // 20

static constexpr int PREP_BLOCKS = (OUT * K) / 256;   // 1280
static constexpr int MM_BLOCKS   = 1024;              // minmax partial blocks

// smem layout (bytes)
static constexpr int BIAS_OFF = 0;            // 256 floats
static constexpr int SRED_OFF = 1024;         // 2 floats
static constexpr int B_OFF    = 2048;         // 3 stages x 32KB
static constexpr int B_STG    = BN * 128;     // 32768
static constexpr int A_OFF    = B_OFF + 3 * B_STG;        // 100352
static constexpr int A_STG    = BM * 128;     // 16384
static constexpr int X_OFF    = A_OFF + 2 * A_STG;        // 133120
static constexpr int X_STG    = BM * 272;     // 34816 (68-float padded rows)
static constexpr int GEMM_SMEM = X_OFF + 2 * X_STG;       // 202752

// K-permutation: k' = q*256 + l*8 + e, original k = 40l + r, r = 8q + e,
// i = l*8 + r/5, g = r%5.  W is stored through this permutation; the A tile
// is GENERATED inside the GEMM through the same permutation.

// ---------------- device globals (scratch; no allocations allowed) ----------
__device__ float  g_pmin[MM_BLOCKS];
__device__ float  g_pmax[MM_BLOCKS];
__device__ __half g_W[OUT * K];              // coef*scale fp16, permuted k

__device__ __forceinline__ void cp_async16(void* smem_dst, const void* gsrc) {
    uint32_t s = (uint32_t)__cvta_generic_to_shared(smem_dst);
    asm volatile("cp.async.cg.shared.global [%0], [%1], 16;\n"
                 :: "r"(s), "l"(gsrc));
}
#define CP_COMMIT() asm volatile("cp.async.commit_group;\n" ::: "memory")
#define CP_WAIT(n)  asm volatile("cp.async.wait_group %0;\n" :: "n"(n) : "memory")

__device__ __forceinline__ uint32_t swz(uint32_t b) {
    return b ^ ((b >> 3) & 0x70);
}

__device__ __forceinline__ void ldm_x4(uint32_t* r, uint32_t addr) {
    asm volatile(
        "ldmatrix.sync.aligned.m8n8.x4.shared.b16 {%0,%1,%2,%3}, [%4];"
        : "=r"(r[0]), "=r"(r[1]), "=r"(r[2]), "=r"(r[3]) : "r"(addr));
}

// ---------------- kernel 1: prep W (blocks 0..1279) + minmax partials -------
__global__ __launch_bounds__(256)
void pre_kernel(const float* __restrict__ x,
                const float* __restrict__ coef,
                const float* __restrict__ scale,
                int n4) {
    const int blk = blockIdx.x;
    const int tid = threadIdx.x;

    if (blk < PREP_BLOCKS) {
        int idx = blk * 256 + tid;
        int o   = idx / K;
        int kp  = idx % K;
        int q   = kp >> 8;
        int rem = kp & 255;
        int l   = rem >> 3;
        int e   = rem & 7;
        int r   = q * 8 + e;
        int j   = r / G;
        int g   = r % G;
        int i   = l * 8 + j;
        g_W[idx] = __float2half(coef[o * K + i * G + g] * scale[o * IN + i]);
        return;
    }

    const int pb = blk - PREP_BLOCKS;
    const float4* x4 = (const float4*)x;
    float lmin =  3.4e38f;
    float lmax = -3.4e38f;
    for (int i = pb * 256 + tid; i < n4; i += MM_BLOCKS * 256) {
        float4 v = x4[i];
        lmin = fminf(lmin, fminf(fminf(v.x, v.y), fminf(v.z, v.w)));
        lmax = fmaxf(lmax, fmaxf(fmaxf(v.x, v.y), fmaxf(v.z, v.w)));
    }
    #pragma unroll
    for (int off = 16; off > 0; off >>= 1) {
        lmin = fminf(lmin, __shfl_xor_sync(0xFFFFFFFFu, lmin, off));
        lmax = fmaxf(lmax, __shfl_xor_sync(0xFFFFFFFFu, lmax, off));
    }
    __shared__ float smin[8], smax[8];
    int warp = tid >> 5, lane = tid & 31;
    if (lane == 0) { smin[warp] = lmin; smax[warp] = lmax; }
    __syncthreads();
    if (warp == 0) {
        lmin = (lane < 8) ? smin[lane] :  3.4e38f;
        lmax = (lane < 8) ? smax[lane] : -3.4e38f;
        #pragma unroll
        for (int off = 4; off > 0; off >>= 1) {
            lmin = fminf(lmin, __shfl_xor_sync(0xFFFFFFFFu, lmin, off));
            lmax = fmaxf(lmax, __shfl_xor_sync(0xFFFFFFFFu, lmax, off));
        }
        if (lane == 0) { g_pmin[pb] = lmin; g_pmax[pb] = lmax; }
    }
}

// ---------------- basis tile generator (Q compile-time => static indexing) --
template<int Q>
__device__ __forceinline__ void basis_tile(const float* __restrict__ xq,
                                           char* __restrict__ adst,
                                           int tid, float s2, float c0,
                                           const float* gr) {
    const int row = tid >> 1;
    const int h   = tid & 1;
    const float* xrow = xq + row * 68;
    constexpr int JB = (8 * Q) / 5;
    constexpr int JT = (8 * Q + 7) / 5;
    #pragma unroll
    for (int ll = 0; ll < 4; ++ll) {
        const int l_local = 4 * h + ll;
        float bv[JT - JB + 1][5];
        #pragma unroll
        for (int jj = 0; jj <= JT - JB; ++jj) {
            float xv = xrow[l_local * 8 + (JB + jj)];
            float xn = fmaf(xv, s2, c0);
            float bb[5];
            float bsum = EPSF;
            #pragma unroll
            for (int g = 0; g < 5; ++g) {
                float s = xn - gr[g];
                float t = s * s;
                float v = fmaxf(fmaf(-t, fabsf(s), 1.0f), 0.0f);
                bb[g] = v;
                bsum += v;
            }
            float inv = 1.0f / bsum;
            #pragma unroll
            for (int g = 0; g < 5; ++g) bv[jj][g] = bb[g] * inv;
        }
        float ev[8];
        #pragma unroll
        for (int e = 0; e < 8; ++e) {
            const int r = 8 * Q + e;            // constant per unrolled e
            ev[e] = bv[r / 5 - JB][r % 5];      // static indices
        }
        __half2 p0 = __floats2half2_rn(ev[0], ev[1]);
        __half2 p1 = __floats2half2_rn(ev[2], ev[3]);
        __half2 p2 = __floats2half2_rn(ev[4], ev[5]);
        __half2 p3 = __floats2half2_rn(ev[6], ev[7]);
        uint4 u;
        u.x = *(uint32_t*)&p0;
        u.y = *(uint32_t*)&p1;
        u.z = *(uint32_t*)&p2;
        u.w = *(uint32_t*)&p3;
        *(uint4*)(adst + swz(row * 128 + l_local * 16)) = u;
    }
}

// ---------------- kernel 2: fused basis + fp16 GEMM -------------------------
// C[b][o] = sum_k basis[b][k] * W[o][k] + bias[o]
// 8 warps of 64x64 (wm=(warp>>2)*64, wn=(warp&3)*64), reg-double-buffered.
__global__ __launch_bounds__(256, 1)
void kan_gemm_kernel(const float* __restrict__ bias,
                     const float* __restrict__ grid,
                     const float* __restrict__ x,
                     float* __restrict__ out) {
    extern __shared__ __align__(16) char smem_raw[];
    float* bias_s = (float*)(smem_raw + BIAS_OFF);
    float* sred   = (float*)(smem_raw + SRED_OFF);

    const int tid = threadIdx.x;
    const int bm0 = blockIdx.x * BM;
    const int warp = tid >> 5, lane = tid & 31;

    bias_s[tid] = bias[tid];

    // reduce minmax partials
    {
        float lmin =  3.4e38f;
        float lmax = -3.4e38f;
        #pragma unroll
        for (int p = 0; p < MM_BLOCKS / 256; ++p) {
            lmin = fminf(lmin, g_pmin[p * 256 + tid]);
            lmax = fmaxf(lmax, g_pmax[p * 256 + tid]);
        }
        #pragma unroll
        for (int off = 16; off > 0; off >>= 1) {
            lmin = fminf(lmin, __shfl_xor_sync(0xFFFFFFFFu, lmin, off));
            lmax = fmaxf(lmax, __shfl_xor_sync(0xFFFFFFFFu, lmax, off));
        }
        __shared__ float wmin[8], wmax[8];
        if (lane == 0) { wmin[warp] = lmin; wmax[warp] = lmax; }
        __syncthreads();
        if (tid == 0) {
            float mn = wmin[0], mx = wmax[0];
            #pragma unroll
            for (int w = 1; w < 8; ++w) {
                mn = fminf(mn, wmin[w]);
                mx = fmaxf(mx, wmax[w]);
            }
            sred[0] = mn;
            sred[1] = mx;
        }
        __syncthreads();
    }
    const float xmin = sred[0];
    const float xmax = sred[1];
    const float s2 = 2.0f / (xmax - xmin + EPSF);
    const float c0 = -xmin * s2 - 1.0f;

    float gr[G];
    #pragma unroll
    for (int g = 0; g < G; ++g) gr[g] = __ldg(grid + g);

    const int wm = (warp >> 2) * 64;
    const int wn = (warp & 3) * 64;

    uint32_t aoff[4], boff[4];
    #pragma unroll
    for (int mi = 0; mi < 4; ++mi) {
        int row = wm + mi * 16 + (lane & 15);
        aoff[mi] = row * 128 + ((lane >> 4) * 16);
    }
    #pragma unroll
    for (int ni = 0; ni < 4; ++ni) {
        int row = wn + ni * 16 + (lane & 7) + ((lane >> 4) << 3);
        boff[ni] = row * 128 + (((lane >> 3) & 1) << 4);
    }

    float acc[4][8][4];
    #pragma unroll
    for (int mi = 0; mi < 4; ++mi)
        #pragma unroll
        for (int nf = 0; nf < 8; ++nf)
            #pragma unroll
            for (int q = 0; q < 4; ++q) acc[mi][nf][q] = 0.0f;

    auto load_B = [&](int ic) {
        char* bb = smem_raw + B_OFF + (ic % 3) * B_STG;
        #pragma unroll
        for (int q = 0; q < 8; ++q) {
            int idx = q * 256 + tid;
            int row = idx >> 3;
            int c   = idx & 7;
            cp_async16(bb + swz(row * 128 + c * 16),
                       g_W + (size_t)row * K + ic * BK + c * 8);
        }
    };
    auto load_X = [&](int jc) {
        char* xd = smem_raw + X_OFF + (jc & 1) * X_STG;
        const int t = jc & 3;
        #pragma unroll
        for (int q = 0; q < 8; ++q) {
            int idx = q * 256 + tid;
            int row = idx >> 4;
            int c   = idx & 15;
            cp_async16(xd + row * 272 + c * 16,
                       x + (size_t)(bm0 + row) * IN + t * 64 + c * 4);
        }
    };
    auto compute_basis = [&](int jc) {
        const float* xq = (const float*)(smem_raw + X_OFF + (jc & 1) * X_STG);
        char* adst = smem_raw + A_OFF + (jc & 1) * A_STG;
        switch (jc >> 2) {
            case 0: basis_tile<0>(xq, adst, tid, s2, c0, gr); break;
            case 1: basis_tile<1>(xq, adst, tid, s2, c0, gr); break;
            case 2: basis_tile<2>(xq, adst, tid, s2, c0, gr); break;
            case 3: basis_tile<3>(xq, adst, tid, s2, c0, gr); break;
            default: basis_tile<4>(xq, adst, tid, s2, c0, gr); break;
        }
    };

    uint32_t afr[2][4][4], bfr[2][4][4];

    auto frag_load = [&](int ic, int ks, int buf) {
        const uint32_t ab = (uint32_t)__cvta_generic_to_shared(
            smem_raw + A_OFF + (ic & 1) * A_STG);
        const uint32_t bb = (uint32_t)__cvta_generic_to_shared(
            smem_raw + B_OFF + (ic % 3) * B_STG);
        const uint32_t kc = (uint32_t)(ks * 32);
        #pragma unroll
        for (int mi = 0; mi < 4; ++mi)
            ldm_x4(afr[buf][mi], ab + swz(aoff[mi] + kc));
        #pragma unroll
        for (int ni = 0; ni < 4; ++ni)
            ldm_x4(bfr[buf][ni], bb + swz(boff[ni] + kc));
    };

    auto mma_step = [&](int buf) {
        #pragma unroll
        for (int mi = 0; mi < 4; ++mi)
            #pragma unroll
            for (int nf = 0; nf < 8; ++nf) {
                const uint32_t b0 = bfr[buf][nf >> 1][(nf & 1) * 2];
                const uint32_t b1 = bfr[buf][nf >> 1][(nf & 1) * 2 + 1];
                asm volatile(
                    "mma.sync.aligned.m16n8k16.row.col.f32.f16.f16.f32 "
                    "{%0,%1,%2,%3}, {%4,%5,%6,%7}, {%8,%9}, {%0,%1,%2,%3};"
                    : "+f"(acc[mi][nf][0]), "+f"(acc[mi][nf][1]),
                      "+f"(acc[mi][nf][2]), "+f"(acc[mi][nf][3])
                    : "r"(afr[buf][mi][0]), "r"(afr[buf][mi][1]),
                      "r"(afr[buf][mi][2]), "r"(afr[buf][mi][3]),
                      "r"(b0), "r"(b1));
            }
    };

    // prologue
    load_X(0);
    CP_COMMIT();                          // G_a: x(0)
    load_B(0);
    load_B(1);
    load_X(1);
    CP_COMMIT();                          // G_b: B0, B1, x(1)
    CP_WAIT(1);
    __syncthreads();                      // x(0) visible
    compute_basis(0);                     // -> As[0]
    CP_WAIT(0);
    __syncthreads();                      // B0, B1, x(1), basis(0) visible
    frag_load(0, 0, 0);

    int cur = 0;
    for (int ic = 0; ic < NCH; ++ic) {
        if (ic + 2 < NCH) { load_B(ic + 2); load_X(ic + 2); }
        CP_COMMIT();                      // G_ic (possibly empty)

        // ksteps 0..2 with register prefetch
        #pragma unroll
        for (int ks = 0; ks < 3; ++ks) {
            const int nxt = cur ^ 1;
            frag_load(ic, ks + 1, nxt);
            mma_step(cur);
            cur = nxt;
        }

        CP_WAIT(1);
        __syncthreads();                  // x(ic+1), B(ic+1) visible

        if (ic + 1 < NCH) compute_basis(ic + 1);   // overlaps tensor drain
        __syncthreads();                  // basis STS visible

        const int nxt = cur ^ 1;
        if (ic + 1 < NCH) frag_load(ic + 1, 0, nxt);
        mma_step(cur);                    // ks3
        cur = nxt;
    }

    // epilogue: + bias, float2 stores
    #pragma unroll
    for (int mi = 0; mi < 4; ++mi) {
        int r = bm0 + wm + mi * 16 + (lane >> 2);
        #pragma unroll
        for (int nf = 0; nf < 8; ++nf) {
            int cl = wn + nf * 8 + ((lane & 3) << 1);
            float b0 = bias_s[cl];
            float b1 = bias_s[cl + 1];
            float2 v0 = make_float2(acc[mi][nf][0] + b0, acc[mi][nf][1] + b1);
            float2 v1 = make_float2(acc[mi][nf][2] + b0, acc[mi][nf][3] + b1);
            *(float2*)(out + (size_t)r * OUT + cl) = v0;
            *(float2*)(out + (size_t)(r + 8) * OUT + cl) = v1;
        }
    }
}

// ---------------------------------------------------------------------------
extern "C" void kernel_launch(void* const* d_in, const int* in_sizes, int n_in,
                              void* d_out, int out_size) {
    const float* x     = (const float*)d_in[0];
    const float* grid  = (const float*)d_in[1];
    const float* coef  = (const float*)d_in[2];
    const float* scale = (const float*)d_in[3];
    const float* bias  = (const float*)d_in[4];
    float* out = (float*)d_out;

    const int B = in_sizes[0] / IN;

    cudaFuncSetAttribute(kan_gemm_kernel,
                         cudaFuncAttributeMaxDynamicSharedMemorySize,
                         GEMM_SMEM);

    pre_kernel<<<PREP_BLOCKS + MM_BLOCKS, 256>>>(x, coef, scale,
                                                 in_sizes[0] / 4);
    kan_gemm_kernel<<<B / BM, 256, GEMM_SMEM>>>(bias, grid, x, out);
}